// round 1
// baseline (speedup 1.0000x reference)
#include <cuda_runtime.h>

#define NEGV (-1e30f)

__device__ __forceinline__ float4 fmax4(float4 a, float4 b) {
    a.x = fmaxf(a.x, b.x);
    a.y = fmaxf(a.y, b.y);
    a.z = fmaxf(a.z, b.z);
    a.w = fmaxf(a.w, b.w);
    return a;
}

// One warp per (b,l) token.
// Lane p holds paths[b][l][p] (P == 32), broadcast with shfl.
// Each lane owns float4 columns {lane, lane+32} of the D=256 row
// -> each gathered row is two coalesced 512B LDG.128 ops.
__global__ __launch_bounds__(256) void path_max_kernel(
    const float* __restrict__ inputs,   // [B,L,D] f32
    const int*   __restrict__ lpaths,   // [B,L,P]
    const int*   __restrict__ rpaths,   // [B,L,P]
    const int*   __restrict__ llens,    // [B,L]
    const int*   __restrict__ rlens,    // [B,L]
    const int*   __restrict__ slens,    // [B]
    float*       __restrict__ out)      // [B,L,2D]
{
    constexpr int L = 512, P = 32, D = 256;

    const int warp = (blockIdx.x * blockDim.x + threadIdx.x) >> 5;
    const int lane = threadIdx.x & 31;
    const int b = warp >> 9;        // warp / L
    const int l = warp & (L - 1);   // warp % L

    // 512 output floats per token = 128 float4
    float4* o4 = reinterpret_cast<float4*>(out) + (size_t)warp * 128;

    if (l >= __ldg(&slens[b])) {
        const float4 z = make_float4(0.f, 0.f, 0.f, 0.f);
        o4[lane]      = z;
        o4[lane + 32] = z;
        o4[lane + 64] = z;
        o4[lane + 96] = z;
        return;
    }

    const float4* base =
        reinterpret_cast<const float4*>(inputs) + (size_t)b * L * (D / 4);

    const int lp = lpaths[(size_t)warp * P + lane];
    const int rp = rpaths[(size_t)warp * P + lane];
    const int ll = llens[warp];
    const int rl = rlens[warp];

    // ---- left path max ----
    float4 m0 = make_float4(NEGV, NEGV, NEGV, NEGV);
    float4 m1 = m0;
    #pragma unroll 2
    for (int p = 0; p < ll; ++p) {
        const int idx = __shfl_sync(0xffffffffu, lp, p);
        const float4* row = base + idx * (D / 4);
        m0 = fmax4(m0, __ldg(&row[lane]));
        m1 = fmax4(m1, __ldg(&row[lane + 32]));
    }
    o4[lane]      = m0;
    o4[lane + 32] = m1;

    // ---- right path max ----
    m0 = make_float4(NEGV, NEGV, NEGV, NEGV);
    m1 = m0;
    #pragma unroll 2
    for (int p = 0; p < rl; ++p) {
        const int idx = __shfl_sync(0xffffffffu, rp, p);
        const float4* row = base + idx * (D / 4);
        m0 = fmax4(m0, __ldg(&row[lane]));
        m1 = fmax4(m1, __ldg(&row[lane + 32]));
    }
    o4[lane + 64] = m0;
    o4[lane + 96] = m1;
}

extern "C" void kernel_launch(void* const* d_in, const int* in_sizes, int n_in,
                              void* d_out, int out_size) {
    const float* inputs = (const float*)d_in[0];
    const int*   lpaths = (const int*)d_in[1];
    const int*   rpaths = (const int*)d_in[2];
    const int*   llens  = (const int*)d_in[3];
    const int*   rlens  = (const int*)d_in[4];
    const int*   slens  = (const int*)d_in[5];

    const int B = in_sizes[5];          // sent_lens has B elements
    const int tokens = B * 512;         // one warp per token
    const int threads = 256;            // 8 warps / block
    const int blocks = (tokens * 32 + threads - 1) / threads;

    path_max_kernel<<<blocks, threads>>>(inputs, lpaths, rpaths,
                                         llens, rlens, slens,
                                         (float*)d_out);
}

// round 2
// speedup vs baseline: 1.1234x; 1.1234x over previous
#include <cuda_runtime.h>

#define NEGV (-1e30f)

__device__ __forceinline__ float4 fmax4(float4 a, float4 b) {
    a.x = fmaxf(a.x, b.x);
    a.y = fmaxf(a.y, b.y);
    a.z = fmaxf(a.z, b.z);
    a.w = fmaxf(a.w, b.w);
    return a;
}

// One block (128 threads = 4 warps) per (b,l) token.
//   warp 0: left  path, d[  0:128)
//   warp 1: left  path, d[128:256)
//   warp 2: right path, d[  0:128)
//   warp 3: right path, d[128:256)
// Lane p holds paths[token][p] (P == 32); broadcast via independent shfls
// so unrolled iterations keep multiple gather LDG.128s in flight.
__global__ __launch_bounds__(128) void path_max_kernel(
    const float* __restrict__ inputs,   // [B,L,D] f32, D=256
    const int*   __restrict__ lpaths,   // [B,L,P]
    const int*   __restrict__ rpaths,   // [B,L,P]
    const int*   __restrict__ llens,    // [B,L]
    const int*   __restrict__ rlens,    // [B,L]
    const int*   __restrict__ slens,    // [B]
    float*       __restrict__ out)      // [B,L,2D]
{
    constexpr int L = 512, P = 32;

    const int token = blockIdx.x;
    const int warp  = threadIdx.x >> 5;
    const int lane  = threadIdx.x & 31;
    const int side  = warp >> 1;     // 0 = left, 1 = right
    const int half  = warp & 1;      // 0 = d[0:128), 1 = d[128:256)
    const int b     = token >> 9;    // token / L
    const int l     = token & (L - 1);

    // Output quadrant: token row has 512 floats = 128 float4.
    float4* o4 = reinterpret_cast<float4*>(out)
               + (size_t)token * 128 + side * 64 + half * 32 + lane;

    if (l >= __ldg(&slens[b])) {
        *o4 = make_float4(0.f, 0.f, 0.f, 0.f);
        return;
    }

    const int* __restrict__ paths = side ? rpaths : lpaths;
    const int len = side ? __ldg(&rlens[token]) : __ldg(&llens[token]);
    const int my  = __ldg(&paths[(size_t)token * P + lane]);

    // Each row of inputs[b] is 64 float4; this warp reads float4 column
    // (half*32 + lane) of each gathered row -> coalesced 512B per LDG.128.
    const float4* __restrict__ base =
        reinterpret_cast<const float4*>(inputs)
        + (size_t)b * L * 64 + half * 32 + lane;

    float4 m = make_float4(NEGV, NEGV, NEGV, NEGV);

    int idx = __shfl_sync(0xffffffffu, my, 0);
    #pragma unroll 4
    for (int p = 0; p < len; ++p) {
        const float4 v = __ldg(base + (size_t)idx * 64);
        idx = __shfl_sync(0xffffffffu, my, (p + 1) & 31);  // independent of v
        m = fmax4(m, v);
    }

    *o4 = m;
}

extern "C" void kernel_launch(void* const* d_in, const int* in_sizes, int n_in,
                              void* d_out, int out_size) {
    const float* inputs = (const float*)d_in[0];
    const int*   lpaths = (const int*)d_in[1];
    const int*   rpaths = (const int*)d_in[2];
    const int*   llens  = (const int*)d_in[3];
    const int*   rlens  = (const int*)d_in[4];
    const int*   slens  = (const int*)d_in[5];

    const int B = in_sizes[5];      // sent_lens has B elements
    const int tokens = B * 512;     // one block per token

    path_max_kernel<<<tokens, 128>>>(inputs, lpaths, rpaths,
                                     llens, rlens, slens,
                                     (float*)d_out);
}